// round 3
// baseline (speedup 1.0000x reference)
#include <cuda_runtime.h>
#include <math.h>

// RoIPooling: feature_map [B,C,FH,FW] f32, rois [N,5] f32 (bidx,x1,y1,x2,y2),
// img scalars -> out [N,C,7,7] f32.   Bench: B=2, C=256, FH=FW=50, N=128, IMG=800.
//
// Layout-first design:
//   1) transpose feat -> featT[B][H*W][C]   (channels contiguous)
//   2) block-per-bin main kernel: thread=channel, zero divergence, coalesced LDG
//   3) transpose outT[n*49][C] -> out[N][C][49]

#define C_DIM 256
#define FH 50
#define FW 50
#define NPIX (FH * FW)
#define OH 7
#define OW 7
#define MAX_B 4
#define MAX_ROIS 512

__device__ float g_featT[MAX_B * NPIX * C_DIM];            // [b][p][c]
__device__ float g_outT[MAX_ROIS * OH * OW * C_DIM];       // [bin][c]

__device__ __forceinline__ float decode_dim(const void* p) {
    int v = *reinterpret_cast<const int*>(p);
    if (v > 0 && v < 1000000) return (float)v;   // int scalar (800 = 0x320)
    return __int_as_float(v);                     // float bits
}

// ---- feat [b][c][p] -> featT [b][p][c] ----
__global__ void transpose_in(const float* __restrict__ feat) {
    __shared__ float t[32][33];
    int b = blockIdx.z;
    int p = blockIdx.x * 32 + threadIdx.x;
    #pragma unroll
    for (int j = 0; j < 32; j += 8) {
        int c = blockIdx.y * 32 + threadIdx.y + j;
        if (p < NPIX)
            t[threadIdx.y + j][threadIdx.x] = feat[((size_t)b * C_DIM + c) * NPIX + p];
    }
    __syncthreads();
    int c2 = blockIdx.y * 32 + threadIdx.x;
    #pragma unroll
    for (int j = 0; j < 32; j += 8) {
        int p2 = blockIdx.x * 32 + threadIdx.y + j;
        if (p2 < NPIX)
            g_featT[((size_t)b * NPIX + p2) * C_DIM + c2] = t[threadIdx.x][threadIdx.y + j];
    }
}

// ---- one block per (n, oh, ow) bin; thread = channel ----
__global__ void roipool_main(const float* __restrict__ rois,
                             const void* __restrict__ img_h_p,
                             const void* __restrict__ img_w_p) {
    int bin = blockIdx.x;
    int c = threadIdx.x;
    int ow = bin % OW;
    int oh = (bin / OW) % OH;
    int n  = bin / (OW * OH);

    __shared__ int s_bounds;   // packed ys|ye|xs|xe
    __shared__ int s_base;     // b * NPIX * C_DIM

    if (c == 0) {
        float img_h = decode_dim(img_h_p);
        float img_w = decode_dim(img_w_p);
        float sh = __fdiv_rn((float)FH, img_h);
        float sw = __fdiv_rn((float)FW, img_w);

        const float* r = rois + n * 5;
        int bidx = (int)r[0];
        // exact reference rounding: single rn-multiply, floor, clamps
        int x1 = max((int)floorf(__fmul_rn(r[1], sw)), 0);
        int y1 = max((int)floorf(__fmul_rn(r[2], sh)), 0);
        int x2 = min((int)floorf(__fmul_rn(r[3], sw)), FW);
        int y2 = min((int)floorf(__fmul_rn(r[4], sh)), FH);

        float bh = __fdiv_rn((float)max(y2 - y1, 1), (float)OH);
        float bw = __fdiv_rn((float)max(x2 - x1, 1), (float)OW);
        float y1f = (float)y1, x1f = (float)x1;
        // mul then add, each rn (no FMA contraction) — matches jnp
        int ys = (int)floorf(__fadd_rn(y1f, __fmul_rn((float)oh,       bh)));
        int ye = (int)floorf(__fadd_rn(y1f, __fmul_rn((float)(oh + 1), bh)));
        int xs = (int)floorf(__fadd_rn(x1f, __fmul_rn((float)ow,       bw)));
        int xe = (int)floorf(__fadd_rn(x1f, __fmul_rn((float)(ow + 1), bw)));
        ys = min(max(ys, 0), FH - 1);
        ye = min(max(ye, 0), FH);
        xs = min(max(xs, 0), FW - 1);
        xe = min(max(xe, 0), FW);
        s_bounds = ys | (ye << 8) | (xs << 16) | (xe << 24);
        s_base = bidx * (NPIX * C_DIM);
    }
    __syncthreads();

    int pb = s_bounds;
    int ys =  pb        & 0xFF;
    int ye = (pb >> 8)  & 0xFF;
    int xs = (pb >> 16) & 0xFF;
    int xe = (pb >> 24) & 0xFF;

    const float* base = g_featT + s_base + c;

    float m = -INFINITY;
    for (int y = ys; y < ye; ++y) {
        const float* rowp = base + (y * FW) * C_DIM;
        #pragma unroll 4
        for (int x = xs; x < xe; ++x) {
            m = fmaxf(m, __ldg(rowp + x * C_DIM));
        }
    }
    bool valid = (ye > ys) && (xe > xs);
    g_outT[(size_t)bin * C_DIM + c] = valid ? m : 0.0f;
}

// ---- outT [n*49][c] -> out [n][c][49] ----
__global__ void transpose_out(float* __restrict__ out) {
    __shared__ float t[32][33];
    int n = blockIdx.z;
    int c = blockIdx.y * 32 + threadIdx.x;
    #pragma unroll
    for (int j = 0; j < 32; j += 8) {
        int q = blockIdx.x * 32 + threadIdx.y + j;
        if (q < OH * OW)
            t[threadIdx.y + j][threadIdx.x] =
                g_outT[((size_t)n * (OH * OW) + q) * C_DIM + c];
    }
    __syncthreads();
    int q2 = blockIdx.x * 32 + threadIdx.x;
    #pragma unroll
    for (int j = 0; j < 32; j += 8) {
        int c2 = blockIdx.y * 32 + threadIdx.y + j;
        if (q2 < OH * OW)
            out[((size_t)n * C_DIM + c2) * (OH * OW) + q2] = t[threadIdx.x][threadIdx.y + j];
    }
}

extern "C" void kernel_launch(void* const* d_in, const int* in_sizes, int n_in,
                              void* d_out, int out_size) {
    const float* feat = (const float*)d_in[0];
    const float* rois = (const float*)d_in[1];
    const void*  imh  = d_in[2];
    const void*  imw  = d_in[3];
    float* out = (float*)d_out;

    int B = in_sizes[0] / (C_DIM * NPIX);
    int nrois = in_sizes[1] / 5;
    int nbins = nrois * OH * OW;

    dim3 tb(32, 8);
    dim3 tg((NPIX + 31) / 32, C_DIM / 32, B);
    transpose_in<<<tg, tb>>>(feat);

    roipool_main<<<nbins, C_DIM>>>(rois, imh, imw);

    dim3 og((OH * OW + 31) / 32, C_DIM / 32, nrois);
    transpose_out<<<og, tb>>>(out);
}